// round 5
// baseline (speedup 1.0000x reference)
#include <cuda_runtime.h>
#include <cuda_bf16.h>

#define BATCH     2048
#define NCLASSES  50257
#define KPOS      20
#define TPB       256

// Per-row loss scratch (allocation-free requirement -> __device__ global).
__device__ float g_row_loss[BATCH];

__device__ __forceinline__ float softplus_f(float x) {
    // log(1+exp(x)) = max(x,0) + log(1+exp(-|x|)); exp arg in (-inf,0] -> value in (0,1]
    return fmaxf(x, 0.0f) + __logf(1.0f + __expf(-fabsf(x)));
}

// Process one float4: accumulate max(x,0) linearly, fold log-terms into products.
// Each factor is in (1,2]; caller takes a log every <=16 factors (prod <= 2^16).
#define PROC4(v)                                                        \
    do {                                                                \
        lin += fmaxf((v).x, 0.0f) + fmaxf((v).y, 0.0f)                  \
             + fmaxf((v).z, 0.0f) + fmaxf((v).w, 0.0f);                 \
        p0 *= (1.0f + __expf(-fabsf((v).x)))                            \
            * (1.0f + __expf(-fabsf((v).y)));                           \
        p1 *= (1.0f + __expf(-fabsf((v).z)))                            \
            * (1.0f + __expf(-fabsf((v).w)));                           \
    } while (0)

__global__ __launch_bounds__(TPB)
void mlsm_row_kernel(const float* __restrict__ inp, const int* __restrict__ tgt) {
    const int row = blockIdx.x;
    const int tid = threadIdx.x;
    const float* __restrict__ rp = inp + (size_t)row * NCLASSES;

    __shared__ int   s_t[KPOS];
    __shared__ float s_warp[TPB / 32];
    __shared__ float s_total;

    // Stage target indices early (consumed by warp 0 after the reduce).
    if (tid < KPOS) s_t[tid] = tgt[row * KPOS + tid];

    // Row base is only 4B-aligned (NCLASSES odd). Scalar prologue to 16B alignment.
    const int mis = (int)(((size_t)row * NCLASSES) & 3);
    const int pro = (4 - mis) & 3;

    float acc = 0.0f;
    if (tid < pro) acc += softplus_f(rp[tid]);

    const float4* __restrict__ vp = (const float4*)(rp + pro);
    const int nv = (NCLASSES - pro) >> 2;   // float4 count

    // Main loop: 4 front-batched LDG.128 per iteration (MLP=4), 16 elems/log.
    int i = tid;
    for (; i + 3 * TPB < nv; i += 4 * TPB) {
        float4 a = vp[i];
        float4 b = vp[i + TPB];
        float4 c = vp[i + 2 * TPB];
        float4 d = vp[i + 3 * TPB];
        float lin = 0.0f, p0 = 1.0f, p1 = 1.0f;
        PROC4(a); PROC4(b); PROC4(c); PROC4(d);
        acc += lin + __logf(p0 * p1);       // p0*p1 <= 2^16, safe
    }
    // Vector remainder.
    for (; i < nv; i += TPB) {
        float4 a = vp[i];
        float lin = 0.0f, p0 = 1.0f, p1 = 1.0f;
        PROC4(a);
        acc += lin + __logf(p0 * p1);
    }
    // Scalar tail.
    const int base = pro + (nv << 2);
    for (int j = base + tid; j < NCLASSES; j += TPB)
        acc += softplus_f(rp[j]);

    // Block reduce acc -> s_total (sum of softplus over the whole row).
    const int lane = tid & 31;
    const int wid  = tid >> 5;
    #pragma unroll
    for (int o = 16; o > 0; o >>= 1)
        acc += __shfl_down_sync(0xFFFFFFFFu, acc, o);
    if (lane == 0) s_warp[wid] = acc;
    __syncthreads();
    if (wid == 0) {
        float v = (lane < TPB / 32) ? s_warp[lane] : 0.0f;
        #pragma unroll
        for (int o = 16; o > 0; o >>= 1)
            v += __shfl_down_sync(0xFFFFFFFFu, v, o);
        if (lane == 0) s_total = v;
    }
    __syncthreads();

    // Warp 0: K=20 label handling.
    if (wid == 0) {
        float pos = 0.0f, corr = 0.0f;
        int   nfirst = 0;
        if (lane < KPOS) {
            const int t = s_t[lane];
            const float x = __ldg(rp + t);
            pos = -softplus_f(-x);          // log_sigmoid(x), duplicates counted
            bool first = true;
            #pragma unroll
            for (int j = 0; j < KPOS; ++j)
                if (j < lane && s_t[j] == t) first = false;
            if (first) { corr = softplus_f(x); nfirst = 1; }  // dedup'd correction
        }
        #pragma unroll
        for (int o = 16; o > 0; o >>= 1) {
            pos    += __shfl_down_sync(0xFFFFFFFFu, pos, o);
            corr   += __shfl_down_sync(0xFFFFFFFFu, corr, o);
            nfirst += __shfl_down_sync(0xFFFFFFFFu, nfirst, o);
        }
        if (lane == 0) {
            const float S = s_total;
            // neg_sum = sum over non-label classes of -softplus(x) = corr - S
            const float neg_mean = (corr - S) / (float)(NCLASSES - nfirst);
            const float pos_mean = pos / (float)KPOS;
            g_row_loss[row] = pos_mean + neg_mean;
        }
    }
}

__global__ __launch_bounds__(512)
void mlsm_reduce_kernel(float* __restrict__ out) {
    __shared__ float sh[512];
    float a = 0.0f;
    for (int i = threadIdx.x; i < BATCH; i += 512)
        a += g_row_loss[i];
    sh[threadIdx.x] = a;
    __syncthreads();
    #pragma unroll
    for (int s = 256; s > 0; s >>= 1) {
        if (threadIdx.x < s) sh[threadIdx.x] += sh[threadIdx.x + s];
        __syncthreads();
    }
    if (threadIdx.x == 0)
        out[0] = -sh[0] / (float)BATCH;
}

extern "C" void kernel_launch(void* const* d_in, const int* in_sizes, int n_in,
                              void* d_out, int out_size) {
    // metadata order: inputs fp32 [2048*50257], targets int32 [2048*20].
    const float* inp = (const float*)d_in[0];
    const int*   tgt = (const int*)d_in[1];
    // Defensive: swap if order differs.
    if (n_in >= 2 && in_sizes[0] == BATCH * KPOS && in_sizes[1] == BATCH * NCLASSES) {
        inp = (const float*)d_in[1];
        tgt = (const int*)d_in[0];
    }
    mlsm_row_kernel<<<BATCH, TPB>>>(inp, tgt);
    mlsm_reduce_kernel<<<1, 512>>>((float*)d_out);
}

// round 6
// speedup vs baseline: 1.0071x; 1.0071x over previous
#include <cuda_runtime.h>
#include <cuda_bf16.h>

#define BATCH     2048
#define NCLASSES  50257
#define KPOS      20
#define TPB       256

// Scratch (allocation-free requirement -> __device__ globals).
__device__ float        g_row_loss[BATCH];
__device__ unsigned int g_done = 0;

__device__ __forceinline__ float softplus_f(float x) {
    // log(1+exp(x)) = max(x,0) + log(1+exp(-|x|)); exp arg <= 0 -> value in (0,1]
    return fmaxf(x, 0.0f) + __logf(1.0f + __expf(-fabsf(x)));
}

// Process one float4: accumulate max(x,0) linearly, fold log-terms into products.
// Each factor in (1,2]; caller takes one log per <=16 factors (prod <= 2^16).
#define PROC4(v)                                                        \
    do {                                                                \
        lin += fmaxf((v).x, 0.0f) + fmaxf((v).y, 0.0f)                  \
             + fmaxf((v).z, 0.0f) + fmaxf((v).w, 0.0f);                 \
        p0 *= (1.0f + __expf(-fabsf((v).x)))                            \
            * (1.0f + __expf(-fabsf((v).y)));                           \
        p1 *= (1.0f + __expf(-fabsf((v).z)))                            \
            * (1.0f + __expf(-fabsf((v).w)));                           \
    } while (0)

__global__ __launch_bounds__(TPB)
void mlsm_row_kernel(const float* __restrict__ inp, const int* __restrict__ tgt,
                     float* __restrict__ out) {
    const int row = blockIdx.x;
    const int tid = threadIdx.x;
    const float* __restrict__ rp = inp + (size_t)row * NCLASSES;

    __shared__ int   s_t[KPOS];
    __shared__ float s_warp[TPB / 32];
    __shared__ float s_total;
    __shared__ int   s_last;

    if (tid < KPOS) s_t[tid] = tgt[row * KPOS + tid];

    // Row base only 4B-aligned (NCLASSES odd): scalar prologue to 16B alignment.
    const int mis = (int)(((size_t)row * NCLASSES) & 3);
    const int pro = (4 - mis) & 3;

    float acc = 0.0f;
    if (tid < pro) acc += softplus_f(rp[tid]);

    const float4* __restrict__ vp = (const float4*)(rp + pro);
    const int nv = (NCLASSES - pro) >> 2;

    // Main loop: 4 front-batched streaming LDG.128 (MLP=4), 16 elems per log.
    int i = tid;
    for (; i + 3 * TPB < nv; i += 4 * TPB) {
        float4 a = __ldcs(vp + i);
        float4 b = __ldcs(vp + i + TPB);
        float4 c = __ldcs(vp + i + 2 * TPB);
        float4 d = __ldcs(vp + i + 3 * TPB);
        float lin = 0.0f, p0 = 1.0f, p1 = 1.0f;
        PROC4(a); PROC4(b); PROC4(c); PROC4(d);
        acc += lin + __logf(p0 * p1);
    }
    for (; i < nv; i += TPB) {
        float4 a = __ldcs(vp + i);
        float lin = 0.0f, p0 = 1.0f, p1 = 1.0f;
        PROC4(a);
        acc += lin + __logf(p0 * p1);
    }
    const int base = pro + (nv << 2);
    for (int j = base + tid; j < NCLASSES; j += TPB)
        acc += softplus_f(rp[j]);

    // Block reduce -> s_total (sum of softplus over the row).
    const int lane = tid & 31;
    const int wid  = tid >> 5;
    #pragma unroll
    for (int o = 16; o > 0; o >>= 1)
        acc += __shfl_down_sync(0xFFFFFFFFu, acc, o);
    if (lane == 0) s_warp[wid] = acc;
    __syncthreads();
    if (wid == 0) {
        float v = (lane < TPB / 32) ? s_warp[lane] : 0.0f;
        #pragma unroll
        for (int o = 16; o > 0; o >>= 1)
            v += __shfl_down_sync(0xFFFFFFFFu, v, o);
        if (lane == 0) s_total = v;
    }
    __syncthreads();

    // Warp 0: K=20 label handling -> row loss.
    if (wid == 0) {
        float pos = 0.0f, corr = 0.0f;
        int   nfirst = 0;
        if (lane < KPOS) {
            const int t = s_t[lane];
            const float x = __ldg(rp + t);
            pos = -softplus_f(-x);                 // log_sigmoid, per occurrence
            bool first = true;
            #pragma unroll
            for (int j = 0; j < KPOS; ++j)
                if (j < lane && s_t[j] == t) first = false;
            if (first) { corr = softplus_f(x); nfirst = 1; }  // dedup'd
        }
        #pragma unroll
        for (int o = 16; o > 0; o >>= 1) {
            pos    += __shfl_down_sync(0xFFFFFFFFu, pos, o);
            corr   += __shfl_down_sync(0xFFFFFFFFu, corr, o);
            nfirst += __shfl_down_sync(0xFFFFFFFFu, nfirst, o);
        }
        if (lane == 0) {
            const float neg_mean = (corr - s_total) / (float)(NCLASSES - nfirst);
            g_row_loss[row] = pos / (float)KPOS + neg_mean;
        }
    }
    __syncthreads();   // g_row_loss write (by tid 0) ordered before the fence below

    // Fused final reduce: last CTA to finish sums all row losses (fixed order,
    // deterministic) and resets the counter for the next graph replay.
    if (tid == 0) {
        __threadfence();
        unsigned int old = atomicAdd(&g_done, 1u);
        s_last = (old == BATCH - 1u) ? 1 : 0;
    }
    __syncthreads();
    if (s_last) {
        float a = 0.0f;
        for (int r = tid; r < BATCH; r += TPB)
            a += __ldcg(&g_row_loss[r]);           // bypass L1: cross-CTA data
        #pragma unroll
        for (int o = 16; o > 0; o >>= 1)
            a += __shfl_down_sync(0xFFFFFFFFu, a, o);
        if (lane == 0) s_warp[wid] = a;
        __syncthreads();
        if (wid == 0) {
            float v = (lane < TPB / 32) ? s_warp[lane] : 0.0f;
            #pragma unroll
            for (int o = 16; o > 0; o >>= 1)
                v += __shfl_down_sync(0xFFFFFFFFu, v, o);
            if (lane == 0) {
                out[0] = -v / (float)BATCH;
                g_done = 0;                        // reset for next replay
            }
        }
    }
}

extern "C" void kernel_launch(void* const* d_in, const int* in_sizes, int n_in,
                              void* d_out, int out_size) {
    const float* inp = (const float*)d_in[0];
    const int*   tgt = (const int*)d_in[1];
    if (n_in >= 2 && in_sizes[0] == BATCH * KPOS && in_sizes[1] == BATCH * NCLASSES) {
        inp = (const float*)d_in[1];
        tgt = (const int*)d_in[0];
    }
    mlsm_row_kernel<<<BATCH, TPB>>>(inp, tgt, (float*)d_out);
}